// round 16
// baseline (speedup 1.0000x reference)
#include <cuda_runtime.h>
#include <cuda_fp16.h>
#include <cstdint>

// ---------------- problem constants ----------------
#define WIN     400
#define HOP     100
#define PADL    300
#define T_IN    480000
#define BATCH   32
#define C_OUT   514
#define F_OUT   4803

#define MROWS   512               // C_OUT minus zero-structure channels 257, 513
#define KREAL   400               // 5 uniform chunks of 80
#define NCHUNK  5
#define XPAD    486784

#define TILE_M  64
#define TILE_N  256
#define NT_C    8
#define NT_F    19
#define THREADS 256

// ---------------- device scratch ----------------
__device__ __half g_wh[MROWS * KREAL];
__device__ __half g_wl[MROWS * KREAL];
__device__ __half g_xh[BATCH * (size_t)XPAD];

// ---------------- main-kernel smem layout ----------------
#define SEG_VECS     3238                      // cp16 units (51808 B)
#define SEG_BYTES    51840
#define OFF_SX       0
#define PITCH_A      176                       // 80 fp16 (160B) + 16B pad
#define A_SPLIT      (TILE_M * PITCH_A)        // 11264
#define A_STAGE      (2 * A_SPLIT)             // wh + wl = 22528
#define OFF_AST(s)   (SEG_BYTES + (s) * A_STAGE)
#define SMEM_TOTAL   (SEG_BYTES + 2 * A_STAGE) // 96896 -> 2 CTAs/SM
#define EPI_PITCH    257

// ---------------- fused prep kernel partition ----------------
#define NBW  800                               // 512*400/256
#define NBX  60848                             // 32*486784/256 (exact)
#define EFRM 256
#define ZSEG ((EFRM - 1) * HOP + WIN)          // 25900 floats
#define NBE  (NT_F * BATCH)                    // 608 (both edge channels per block)
#define NB_TOTAL (NBW + NBX + NBE)
#define EDGE_SMEM ((ZSEG + 2 * WIN) * (int)sizeof(float))   // 106800 B

// ---------------- helpers ----------------
__device__ __forceinline__ uint32_t smem_u32(const void* p) {
    uint32_t a;
    asm("{ .reg .u64 t; cvta.to.shared.u64 t, %1; cvt.u32.u64 %0, t; }" : "=r"(a) : "l"(p));
    return a;
}
__device__ __forceinline__ void cp16(uint32_t dst, const void* src) {
    asm volatile("cp.async.cg.shared.global [%0], [%1], 16;" :: "r"(dst), "l"(src));
}
__device__ __forceinline__ void cp_commit() {
    asm volatile("cp.async.commit_group;" ::: "memory");
}
template <int N>
__device__ __forceinline__ void cp_wait() {
    asm volatile("cp.async.wait_group %0;" :: "n"(N) : "memory");
}
__device__ __forceinline__ void ldsm_x4(uint32_t& r0, uint32_t& r1, uint32_t& r2, uint32_t& r3,
                                        uint32_t addr) {
    asm volatile("ldmatrix.sync.aligned.m8n8.x4.shared.b16 {%0,%1,%2,%3}, [%4];"
                 : "=r"(r0), "=r"(r1), "=r"(r2), "=r"(r3) : "r"(addr));
}
__device__ __forceinline__ void lds32(uint32_t& r, uint32_t addr) {
    asm volatile("ld.shared.b32 %0, [%1];" : "=r"(r) : "r"(addr));
}
__device__ __forceinline__ void mma16816(float* d, const uint32_t* a, const uint32_t* b) {
    asm volatile(
        "mma.sync.aligned.m16n8k16.row.col.f32.f16.f16.f32 "
        "{%0,%1,%2,%3}, {%4,%5,%6,%7}, {%8,%9}, {%0,%1,%2,%3};"
        : "+f"(d[0]), "+f"(d[1]), "+f"(d[2]), "+f"(d[3])
        : "r"(a[0]), "r"(a[1]), "r"(a[2]), "r"(a[3]), "r"(b[0]), "r"(b[1]));
}

// ---------------- fused prep kernel: w-split | x-split | edge channels ----------------
__global__ void prep_fused_kernel(const float* __restrict__ x,
                                  const float* __restrict__ w,
                                  float* __restrict__ out)
{
    const int bid = blockIdx.x;
    const int tid = threadIdx.x;

    if (bid < NBW) {
        // ---- weights: fp32 -> (fp16 hi, fp16 lo); row r -> channel c = r + (r>=257)
        int idx = bid * 256 + tid;             // < 204800 = MROWS*KREAL
        int r = idx / KREAL;
        int k = idx - r * KREAL;
        int c = r + (r >= 257);
        float v = w[c * KREAL + k];
        __half h = __float2half(v);
        g_wh[idx] = h;
        g_wl[idx] = __float2half(v - __half2float(h));
        return;
    }
    if (bid < NBW + NBX) {
        // ---- signal: padded fp32 -> fp16
        size_t idx = (size_t)(bid - NBW) * 256 + tid;   // < 15,577,088
        int b = (int)(idx / XPAD);
        int i = (int)(idx - (size_t)b * XPAD);
        int src = i - PADL;
        float v = (src >= 0 && src < T_IN) ? x[(size_t)b * T_IN + src] : 0.0f;
        g_xh[idx] = __float2half(v);
        return;
    }

    // ---- edge channels 257 & 513, exact fp32, both from one shared segment ----
    extern __shared__ float zs[];
    float* sxs = zs;                  // [ZSEG]
    float* sw0 = zs + ZSEG;           // [WIN] ch 257
    float* sw1 = sw0 + WIN;           // [WIN] ch 513
    const int eb = bid - NBW - NBX;
    const int f0 = (eb % NT_F) * EFRM;
    const int b  = eb / NT_F;

    const int base = f0 * HOP - PADL;
    const float* xb = x + (size_t)b * T_IN;
    for (int i = tid; i < ZSEG; i += EFRM) {
        int gi = base + i;
        sxs[i] = (gi >= 0 && gi < T_IN) ? xb[gi] : 0.0f;
    }
    for (int i = tid; i < WIN; i += EFRM) {
        sw0[i] = w[257 * WIN + i];
        sw1[i] = w[513 * WIN + i];
    }
    __syncthreads();

    float a0 = 0.0f, a1 = 0.0f;
    const float* sp = sxs + tid * HOP;
    #pragma unroll 8
    for (int k = 0; k < WIN; k++) {
        float xv = sp[k];
        a0 = fmaf(xv, sw0[k], a0);
        a1 = fmaf(xv, sw1[k], a1);
    }

    int f = f0 + tid;
    if (f < F_OUT) {
        out[((size_t)b * C_OUT + 257) * F_OUT + f] = a0;
        out[((size_t)b * C_OUT + 513) * F_OUT + f] = a1;
    }
}

// ---------------- main HMMA GEMM: 64x256 CTA, 2 CTAs/SM, 32x64 warp tiles ----------------
__global__ __launch_bounds__(THREADS, 2)
void conv_stft_hmma_kernel(float* __restrict__ out)
{
    extern __shared__ char smem[];
    const uint32_t sbase = smem_u32(smem);
    const int tid  = threadIdx.x;
    const int wid  = tid >> 5;
    const int lane = tid & 31;

    const int c0 = blockIdx.x * TILE_M;
    const int f0 = blockIdx.y * TILE_N;
    const int b  = blockIdx.z;

    const char* wh_base = reinterpret_cast<const char*>(g_wh) + (size_t)c0 * (KREAL * 2);
    const char* wl_base = reinterpret_cast<const char*>(g_wl) + (size_t)c0 * (KREAL * 2);
    const char* xh_base = reinterpret_cast<const char*>(g_xh + (size_t)b * XPAD + f0 * HOP);

    // ---- A chunk staging: 64 rows x 80 fp16 (10x16B), both w splits ----
    auto stage_a = [&](int kc, int s) {
        #pragma unroll
        for (int i = tid; i < 2 * TILE_M * 10; i += THREADS) {
            int per = TILE_M * 10;
            int split = i >= per;
            int j = i - split * per;
            int r = j / 10, u = j - r * 10;
            const char* src = (split ? wl_base : wh_base) + r * (KREAL * 2) + kc * 160 + u * 16;
            cp16(sbase + OFF_AST(s) + split * A_SPLIT + r * PITCH_A + u * 16, src);
        }
        cp_commit();
    };

    // ---- prologue: persistent x segment + first A chunk ----
    #pragma unroll 4
    for (int i = tid; i < SEG_VECS; i += THREADS)
        cp16(sbase + OFF_SX + i * 16, xh_base + i * 16);
    stage_a(0, 0);

    // warp layout: 2 (M) x 4 (N); warp tile 32 x 64
    const int m0 = (wid >> 2) * 32;
    const int n0 = (wid & 3) * 64;

    float acc[2][8][4];
    #pragma unroll
    for (int i = 0; i < 2; i++)
        #pragma unroll
        for (int j = 0; j < 8; j++)
            #pragma unroll
            for (int q = 0; q < 4; q++) acc[i][j][q] = 0.0f;

    const uint32_t a_off = (m0 + (lane & 15)) * PITCH_A + (lane >> 4) * 16;
    const uint32_t bfrag0 = sbase + (uint32_t)((n0 + (lane >> 2)) * 200 + (lane & 3) * 4);

    for (int kc = 0; kc < NCHUNK; kc++) {
        const int s = kc & 1;
        cp_wait<0>();
        __syncthreads();
        if (kc + 1 < NCHUNK) stage_a(kc + 1, s ^ 1);

        const uint32_t ah_base = sbase + OFF_AST(s) + a_off;
        const uint32_t al_base = ah_base + A_SPLIT;
        const uint32_t bb_kc   = bfrag0 + kc * 160;

        #pragma unroll
        for (int ks = 0; ks < 5; ks++) {
            uint32_t bh[8][2];
            const uint32_t bb = bb_kc + ks * 32;
            #pragma unroll
            for (int ni = 0; ni < 8; ni++) {
                uint32_t o = bb + ni * 1600;
                lds32(bh[ni][0], o);
                lds32(bh[ni][1], o + 16);
            }
            uint32_t ahf[2][4], alf[2][4];
            ldsm_x4(ahf[0][0], ahf[0][1], ahf[0][2], ahf[0][3], ah_base + ks * 32);
            ldsm_x4(alf[0][0], alf[0][1], alf[0][2], alf[0][3], al_base + ks * 32);
            #pragma unroll
            for (int mi = 0; mi < 2; mi++) {
                const int cur = mi & 1;
                if (mi < 1) {
                    ldsm_x4(ahf[1][0], ahf[1][1], ahf[1][2], ahf[1][3],
                            ah_base + 16 * PITCH_A + ks * 32);
                    ldsm_x4(alf[1][0], alf[1][1], alf[1][2], alf[1][3],
                            al_base + 16 * PITCH_A + ks * 32);
                }
                #pragma unroll
                for (int ni = 0; ni < 8; ni++)
                    mma16816(acc[mi][ni], ahf[cur], bh[ni]);   // w_h * x_h
                #pragma unroll
                for (int ni = 0; ni < 8; ni++)
                    mma16816(acc[mi][ni], alf[cur], bh[ni]);   // w_l * x_h
            }
        }
    }

    // ---- epilogue: registers -> smem transpose -> coalesced stores ----
    __syncthreads();
    float* epi = reinterpret_cast<float*>(smem);
    const int g = lane >> 2;
    const int t = lane & 3;
    #pragma unroll
    for (int mi = 0; mi < 2; mi++)
        #pragma unroll
        for (int ni = 0; ni < 8; ni++) {
            int col = n0 + ni * 8 + t * 2;
            #pragma unroll
            for (int half = 0; half < 2; half++) {
                int row = m0 + mi * 16 + half * 8 + g;
                epi[row * EPI_PITCH + col]     = acc[mi][ni][half * 2];
                epi[row * EPI_PITCH + col + 1] = acc[mi][ni][half * 2 + 1];
            }
        }
    __syncthreads();

    #pragma unroll 4
    for (int idx = tid; idx < TILE_M * TILE_N; idx += THREADS) {
        int row = idx >> 8;
        int col = idx & 255;
        int R = c0 + row;
        int c = R + (R >= 257);
        int f = f0 + col;
        if (f < F_OUT)
            out[((size_t)b * C_OUT + c) * F_OUT + f] = epi[row * EPI_PITCH + col];
    }
}

// ---------------- launcher ----------------
extern "C" void kernel_launch(void* const* d_in, const int* in_sizes, int n_in,
                              void* d_out, int out_size)
{
    const float* x = (const float*)d_in[0];
    const float* w = (const float*)d_in[1];
    float* out = (float*)d_out;

    cudaFuncSetAttribute(prep_fused_kernel,
                         cudaFuncAttributeMaxDynamicSharedMemorySize, EDGE_SMEM);
    prep_fused_kernel<<<NB_TOTAL, 256, EDGE_SMEM>>>(x, w, out);

    cudaFuncSetAttribute(conv_stft_hmma_kernel,
                         cudaFuncAttributeMaxDynamicSharedMemorySize, SMEM_TOTAL);
    dim3 grid(NT_C, NT_F, BATCH);   // 8 x 19 x 32 = 4864 CTAs, 2/SM
    conv_stft_hmma_kernel<<<grid, THREADS, SMEM_TOTAL>>>(out);
}

// round 17
// speedup vs baseline: 1.3202x; 1.3202x over previous
#include <cuda_runtime.h>
#include <cuda_fp16.h>
#include <cstdint>

// ---------------- problem constants ----------------
#define WIN     400
#define HOP     100
#define PADL    300
#define T_IN    480000
#define BATCH   32
#define C_OUT   514
#define F_OUT   4803

#define MROWS   512               // C_OUT minus zero-structure channels 257, 513
#define KREAL   400               // 5 uniform chunks of 80
#define NCHUNK  5
#define XPAD    486784

#define TILE_M  64
#define TILE_N  256
#define NT_C    8
#define NT_F    19
#define THREADS 256

// ---------------- device scratch ----------------
__device__ __half g_wh[MROWS * KREAL];
__device__ __half g_wl[MROWS * KREAL];
__device__ __half g_xh[BATCH * (size_t)XPAD];

// ---------------- main-kernel smem layout ----------------
#define SEG_VECS     3238                      // cp16 units (51808 B)
#define SEG_BYTES    51840
#define OFF_SX       0
#define PITCH_A      176                       // 80 fp16 (160B) + 16B pad
#define A_SPLIT      (TILE_M * PITCH_A)        // 11264
#define A_STAGE      (2 * A_SPLIT)             // wh + wl = 22528
#define OFF_AST(s)   (SEG_BYTES + (s) * A_STAGE)
#define SMEM_TOTAL   (SEG_BYTES + 2 * A_STAGE) // 96896 -> 2 CTAs/SM
#define EPI_PITCH    257

// ---------------- helpers ----------------
__device__ __forceinline__ uint32_t smem_u32(const void* p) {
    uint32_t a;
    asm("{ .reg .u64 t; cvta.to.shared.u64 t, %1; cvt.u32.u64 %0, t; }" : "=r"(a) : "l"(p));
    return a;
}
__device__ __forceinline__ void cp16(uint32_t dst, const void* src) {
    asm volatile("cp.async.cg.shared.global [%0], [%1], 16;" :: "r"(dst), "l"(src));
}
__device__ __forceinline__ void cp_commit() {
    asm volatile("cp.async.commit_group;" ::: "memory");
}
template <int N>
__device__ __forceinline__ void cp_wait() {
    asm volatile("cp.async.wait_group %0;" :: "n"(N) : "memory");
}
__device__ __forceinline__ void ldsm_x4(uint32_t& r0, uint32_t& r1, uint32_t& r2, uint32_t& r3,
                                        uint32_t addr) {
    asm volatile("ldmatrix.sync.aligned.m8n8.x4.shared.b16 {%0,%1,%2,%3}, [%4];"
                 : "=r"(r0), "=r"(r1), "=r"(r2), "=r"(r3) : "r"(addr));
}
__device__ __forceinline__ void lds32(uint32_t& r, uint32_t addr) {
    asm volatile("ld.shared.b32 %0, [%1];" : "=r"(r) : "r"(addr));
}
__device__ __forceinline__ void mma16816(float* d, const uint32_t* a, const uint32_t* b) {
    asm volatile(
        "mma.sync.aligned.m16n8k16.row.col.f32.f16.f16.f32 "
        "{%0,%1,%2,%3}, {%4,%5,%6,%7}, {%8,%9}, {%0,%1,%2,%3};"
        : "+f"(d[0]), "+f"(d[1]), "+f"(d[2]), "+f"(d[3])
        : "r"(a[0]), "r"(a[1]), "r"(a[2]), "r"(a[3]), "r"(b[0]), "r"(b[1]));
}

// ---------------- prep kernels ----------------
__global__ void prep_w_kernel(const float* __restrict__ w) {
    int idx = blockIdx.x * blockDim.x + threadIdx.x;
    if (idx >= MROWS * KREAL) return;
    int r = idx / KREAL;
    int k = idx - r * KREAL;
    int c = r + (r >= 257);
    float v = w[c * KREAL + k];
    __half h = __float2half(v);
    g_wh[idx] = h;
    g_wl[idx] = __float2half(v - __half2float(h));
}

// vectorized: 8 elements per thread (2x float4 load, 1x uint4 store)
#define XGRP (XPAD / 8)            // 60848 groups per batch
__global__ void prep_x_kernel(const float* __restrict__ x) {
    size_t gid = (size_t)blockIdx.x * blockDim.x + threadIdx.x;
    if (gid >= (size_t)BATCH * XGRP) return;
    int b = (int)(gid / XGRP);
    int g = (int)(gid - (size_t)b * XGRP);
    int i0 = g * 8;
    int s0 = i0 - PADL;
    __half hv[8];
    if (s0 >= 0 && s0 + 7 < T_IN) {
        // interior: s0 is 16B-aligned (i0 mult of 8, 300*4 mult of 16)
        const float4* xp = reinterpret_cast<const float4*>(x + (size_t)b * T_IN + s0);
        float4 v0 = xp[0], v1 = xp[1];
        hv[0] = __float2half(v0.x); hv[1] = __float2half(v0.y);
        hv[2] = __float2half(v0.z); hv[3] = __float2half(v0.w);
        hv[4] = __float2half(v1.x); hv[5] = __float2half(v1.y);
        hv[6] = __float2half(v1.z); hv[7] = __float2half(v1.w);
    } else {
        const float* xb = x + (size_t)b * T_IN;
        #pragma unroll
        for (int j = 0; j < 8; j++) {
            int src = s0 + j;
            hv[j] = __float2half((src >= 0 && src < T_IN) ? xb[src] : 0.0f);
        }
    }
    *reinterpret_cast<uint4*>(g_xh + (size_t)b * XPAD + i0) =
        *reinterpret_cast<const uint4*>(hv);
}

// ---------------- exact scalar conv for channels 257 AND 513 per block ----------------
#define EFRM 256
#define ZSEG ((EFRM - 1) * HOP + WIN)          // 25900 floats
#define EDGE_SMEM ((ZSEG + 2 * WIN) * (int)sizeof(float))
__global__ void edge_ch_kernel(const float* __restrict__ x,
                               const float* __restrict__ w,
                               float* __restrict__ out)
{
    extern __shared__ float zs[];
    float* sxs = zs;
    float* sw0 = zs + ZSEG;          // ch 257
    float* sw1 = sw0 + WIN;          // ch 513
    const int f0 = blockIdx.x * EFRM;
    const int b  = blockIdx.y;
    const int tid = threadIdx.x;

    const int base = f0 * HOP - PADL;
    const float* xb = x + (size_t)b * T_IN;
    for (int i = tid; i < ZSEG; i += EFRM) {
        int gi = base + i;
        sxs[i] = (gi >= 0 && gi < T_IN) ? xb[gi] : 0.0f;
    }
    for (int i = tid; i < WIN; i += EFRM) {
        sw0[i] = w[257 * WIN + i];
        sw1[i] = w[513 * WIN + i];
    }
    __syncthreads();

    float a0 = 0.0f, a1 = 0.0f;
    const float* sp = sxs + tid * HOP;
    #pragma unroll 8
    for (int k = 0; k < WIN; k++) {
        float xv = sp[k];
        a0 = fmaf(xv, sw0[k], a0);
        a1 = fmaf(xv, sw1[k], a1);
    }

    int f = f0 + tid;
    if (f < F_OUT) {
        out[((size_t)b * C_OUT + 257) * F_OUT + f] = a0;
        out[((size_t)b * C_OUT + 513) * F_OUT + f] = a1;
    }
}

// ---------------- main HMMA GEMM: 64x256 CTA, 2 CTAs/SM, 32x64 warp tiles ----------------
__global__ __launch_bounds__(THREADS, 2)
void conv_stft_hmma_kernel(float* __restrict__ out)
{
    extern __shared__ char smem[];
    const uint32_t sbase = smem_u32(smem);
    const int tid  = threadIdx.x;
    const int wid  = tid >> 5;
    const int lane = tid & 31;

    const int c0 = blockIdx.x * TILE_M;
    const int f0 = blockIdx.y * TILE_N;
    const int b  = blockIdx.z;

    const char* wh_base = reinterpret_cast<const char*>(g_wh) + (size_t)c0 * (KREAL * 2);
    const char* wl_base = reinterpret_cast<const char*>(g_wl) + (size_t)c0 * (KREAL * 2);
    const char* xh_base = reinterpret_cast<const char*>(g_xh + (size_t)b * XPAD + f0 * HOP);

    // ---- A chunk staging: 64 rows x 80 fp16 (10x16B), both w splits ----
    auto stage_a = [&](int kc, int s) {
        #pragma unroll
        for (int i = tid; i < 2 * TILE_M * 10; i += THREADS) {
            int per = TILE_M * 10;
            int split = i >= per;
            int j = i - split * per;
            int r = j / 10, u = j - r * 10;
            const char* src = (split ? wl_base : wh_base) + r * (KREAL * 2) + kc * 160 + u * 16;
            cp16(sbase + OFF_AST(s) + split * A_SPLIT + r * PITCH_A + u * 16, src);
        }
        cp_commit();
    };

    // ---- prologue: persistent x segment + first A chunk ----
    #pragma unroll 4
    for (int i = tid; i < SEG_VECS; i += THREADS)
        cp16(sbase + OFF_SX + i * 16, xh_base + i * 16);
    stage_a(0, 0);

    // warp layout: 2 (M) x 4 (N); warp tile 32 x 64
    const int m0 = (wid >> 2) * 32;
    const int n0 = (wid & 3) * 64;

    float acc[2][8][4];
    #pragma unroll
    for (int i = 0; i < 2; i++)
        #pragma unroll
        for (int j = 0; j < 8; j++)
            #pragma unroll
            for (int q = 0; q < 4; q++) acc[i][j][q] = 0.0f;

    const uint32_t a_off = (m0 + (lane & 15)) * PITCH_A + (lane >> 4) * 16;
    const uint32_t bfrag0 = sbase + (uint32_t)((n0 + (lane >> 2)) * 200 + (lane & 3) * 4);

    for (int kc = 0; kc < NCHUNK; kc++) {
        const int s = kc & 1;
        cp_wait<0>();
        __syncthreads();
        if (kc + 1 < NCHUNK) stage_a(kc + 1, s ^ 1);

        const uint32_t ah_base = sbase + OFF_AST(s) + a_off;
        const uint32_t al_base = ah_base + A_SPLIT;
        const uint32_t bb_kc   = bfrag0 + kc * 160;

        #pragma unroll
        for (int ks = 0; ks < 5; ks++) {
            uint32_t bh[8][2];
            const uint32_t bb = bb_kc + ks * 32;
            #pragma unroll
            for (int ni = 0; ni < 8; ni++) {
                uint32_t o = bb + ni * 1600;
                lds32(bh[ni][0], o);
                lds32(bh[ni][1], o + 16);
            }
            uint32_t ahf[2][4], alf[2][4];
            ldsm_x4(ahf[0][0], ahf[0][1], ahf[0][2], ahf[0][3], ah_base + ks * 32);
            ldsm_x4(alf[0][0], alf[0][1], alf[0][2], alf[0][3], al_base + ks * 32);
            #pragma unroll
            for (int mi = 0; mi < 2; mi++) {
                const int cur = mi & 1;
                if (mi < 1) {
                    ldsm_x4(ahf[1][0], ahf[1][1], ahf[1][2], ahf[1][3],
                            ah_base + 16 * PITCH_A + ks * 32);
                    ldsm_x4(alf[1][0], alf[1][1], alf[1][2], alf[1][3],
                            al_base + 16 * PITCH_A + ks * 32);
                }
                #pragma unroll
                for (int ni = 0; ni < 8; ni++)
                    mma16816(acc[mi][ni], ahf[cur], bh[ni]);   // w_h * x_h
                #pragma unroll
                for (int ni = 0; ni < 8; ni++)
                    mma16816(acc[mi][ni], alf[cur], bh[ni]);   // w_l * x_h
            }
        }
    }

    // ---- epilogue: registers -> smem transpose -> coalesced stores ----
    __syncthreads();
    float* epi = reinterpret_cast<float*>(smem);
    const int g = lane >> 2;
    const int t = lane & 3;
    #pragma unroll
    for (int mi = 0; mi < 2; mi++)
        #pragma unroll
        for (int ni = 0; ni < 8; ni++) {
            int col = n0 + ni * 8 + t * 2;
            #pragma unroll
            for (int half = 0; half < 2; half++) {
                int row = m0 + mi * 16 + half * 8 + g;
                epi[row * EPI_PITCH + col]     = acc[mi][ni][half * 2];
                epi[row * EPI_PITCH + col + 1] = acc[mi][ni][half * 2 + 1];
            }
        }
    __syncthreads();

    #pragma unroll 4
    for (int idx = tid; idx < TILE_M * TILE_N; idx += THREADS) {
        int row = idx >> 8;
        int col = idx & 255;
        int R = c0 + row;
        int c = R + (R >= 257);
        int f = f0 + col;
        if (f < F_OUT)
            out[((size_t)b * C_OUT + c) * F_OUT + f] = epi[row * EPI_PITCH + col];
    }
}

// ---------------- launcher ----------------
extern "C" void kernel_launch(void* const* d_in, const int* in_sizes, int n_in,
                              void* d_out, int out_size)
{
    const float* x = (const float*)d_in[0];
    const float* w = (const float*)d_in[1];
    float* out = (float*)d_out;

    prep_w_kernel<<<(MROWS * KREAL + 255) / 256, 256>>>(w);
    prep_x_kernel<<<(int)(((size_t)BATCH * XGRP + 255) / 256), 256>>>(x);

    cudaFuncSetAttribute(edge_ch_kernel,
                         cudaFuncAttributeMaxDynamicSharedMemorySize, EDGE_SMEM);
    dim3 zgrid(NT_F, BATCH);          // 19 x 32 = 608 blocks, both channels each
    edge_ch_kernel<<<zgrid, EFRM, EDGE_SMEM>>>(x, w, out);

    cudaFuncSetAttribute(conv_stft_hmma_kernel,
                         cudaFuncAttributeMaxDynamicSharedMemorySize, SMEM_TOTAL);
    dim3 grid(NT_C, NT_F, BATCH);     // 8 x 19 x 32 = 4864 CTAs, 2/SM
    conv_stft_hmma_kernel<<<grid, THREADS, SMEM_TOTAL>>>(out);
}